// round 12
// baseline (speedup 1.0000x reference)
#include <cuda_runtime.h>
#include <math.h>

#define NB 8
#define NC 256
#define HD 128
#define HW (HD*HD)
#define HM 512

#define RES_BLKS (NB*HW/256)   // 512 resize blocks (scheduled FIRST)
#define STAT_BLKS (NB*HW/64)   // 2048 stat blocks

// scratch (allocation-free rule: __device__ globals)
__device__ __align__(16) float g_m[NB*HW];     // resized mask
__device__ __align__(16) float g_avg[NB*HW];   // RAW mean_c(x)  (premult in conv)
__device__ __align__(16) float g_maxp[NB*HW];  // RAW max_c(x)   (premult in conv)
__device__ __align__(16) float g_s[NB*HW];     // m * sigmoid(conv)

// ---------------------------------------------------------------------------
// Fused Kernel A+B: blocks [0,512) do the antialiased 512->128 mask resize
// (scheduled FIRST so they hide under the stat blocks instead of forming a
// tail); blocks [512,2560) do channel mean/max (raw; premult deferred to
// conv). Chanstat: 256 thr = 64 px x 4 ch-groups of 64ch, scalar loads.
// ---------------------------------------------------------------------------
__global__ void __launch_bounds__(256)
k_stat_resize(const float* __restrict__ x, const float* __restrict__ masks) {
    if (blockIdx.x >= RES_BLKS) {
        // ---- chanstat role ----
        __shared__ float s_sum[4][64];
        __shared__ float s_max[4][64];
        int pix = threadIdx.x & 63;
        int cg  = threadIdx.x >> 6;          // 0..3
        int p0  = (blockIdx.x - RES_BLKS) * 64;  // never straddles a batch
        int b   = p0 / HW;
        int hw  = p0 - b * HW + pix;

        const float* xp = x + ((size_t)(b*NC + cg*64)) * HW + hw;
        float s = 0.f, mx = -3.4e38f;
#pragma unroll 16
        for (int c = 0; c < 64; c++) {
            float v = __ldg(xp + (size_t)c * HW);
            s += v;
            mx = fmaxf(mx, v);
        }
        s_sum[cg][pix] = s;
        s_max[cg][pix] = mx;
        __syncthreads();
        if (cg == 0) {
            float S  = s_sum[0][pix] + s_sum[1][pix] + s_sum[2][pix] + s_sum[3][pix];
            float M  = fmaxf(fmaxf(s_max[0][pix], s_max[1][pix]),
                             fmaxf(s_max[2][pix], s_max[3][pix]));
            int g = p0 + pix;
            g_avg[g]  = S * (1.f/NC);
            g_maxp[g] = M;
        }
    } else {
        // ---- resize role: antialiased bilinear (triangle, 8 taps/dim) ----
        int idx = blockIdx.x * 256 + threadIdx.x;
        int b = idx / HW;
        int r = (idx / HD) % HD;
        int q = idx % HD;
        const float raw[8] = {0.125f,0.375f,0.625f,0.875f,0.875f,0.625f,0.375f,0.125f};
        float wr[8], wc[8]; int jr[8], jc[8];
        float tr = 0.f, tc = 0.f;
#pragma unroll
        for (int k = 0; k < 8; k++) {
            int j = 4*r - 2 + k;
            bool ok = (j >= 0) && (j < HM);
            wr[k] = ok ? raw[k] : 0.f;
            jr[k] = ok ? j : 0;
            tr += wr[k];
            j = 4*q - 2 + k;
            ok = (j >= 0) && (j < HM);
            wc[k] = ok ? raw[k] : 0.f;
            jc[k] = ok ? j : 0;
            tc += wc[k];
        }
        const float* mp = masks + (size_t)b * HM * HM;
        float acc = 0.f;
#pragma unroll
        for (int a = 0; a < 8; a++) {
            float rowacc = 0.f;
#pragma unroll
            for (int bb = 0; bb < 8; bb++)
                rowacc += wc[bb] * __ldg(mp + jr[a]*HM + jc[bb]);
            acc += wr[a] * rowacc;
        }
        g_m[idx] = acc / (tr * tc);
    }
}

// ---------------------------------------------------------------------------
// Kernel C: 7x7 conv over [m*avg, m*max, m] (zero pad 3) -> sigmoid ->
// s = m*atten. Premultiply by m happens here while filling smem.
// 16x16 output tile per block, 22x22x3 smem halo tile.
// ---------------------------------------------------------------------------
__global__ void k_conv(const float* __restrict__ cw) {
    __shared__ float sh[3][22][22];
    __shared__ float wsm[3*49];
    int t = threadIdx.x;                 // 256 threads
    int bx = blockIdx.x & 7;
    int by = (blockIdx.x >> 3) & 7;
    int b  = blockIdx.x >> 6;
    int h0 = by*16 - 3, w0 = bx*16 - 3;
    if (t < 147) wsm[t] = cw[t];
    for (int i = t; i < 22*22; i += 256) {
        int ih = i / 22, iw = i % 22;
        int hh = h0 + ih, ww = w0 + iw;
        bool ok = (hh >= 0) && (hh < HD) && (ww >= 0) && (ww < HD);
        if (ok) {
            int g = b*HW + hh*HD + ww;
            float m = g_m[g];
            sh[0][ih][iw] = m * g_avg[g];
            sh[1][ih][iw] = m * g_maxp[g];
            sh[2][ih][iw] = m;
        } else {
            sh[0][ih][iw] = 0.f;
            sh[1][ih][iw] = 0.f;
            sh[2][ih][iw] = 0.f;
        }
    }
    __syncthreads();
    int ty = t >> 4, tx = t & 15;
    float acc = 0.f;
#pragma unroll
    for (int c = 0; c < 3; c++)
#pragma unroll
        for (int kh = 0; kh < 7; kh++)
#pragma unroll
            for (int kw = 0; kw < 7; kw++)
                acc += sh[c][ty+kh][tx+kw] * wsm[c*49 + kh*7 + kw];
    float at = 1.f / (1.f + expf(-acc));
    int h = h0 + 3 + ty, w = w0 + 3 + tx;
    int g = b*HW + h*HD + w;
    g_s[g] = g_m[g] * at;
}

// ---------------------------------------------------------------------------
// Kernel D: per (b,c): out = relu(5 * IN(x*s)). Two-pass with L2 reuse.
// REVERSE batch order: chanstat finishes with tail batches of x hot in L2,
// and norm finishing at batch 0 leaves head batches hot for the NEXT
// iteration's chanstat. Phase 2 re-reads the same 64KB channel (L1/L2-hot;
// max-L1 carveout requested). out written evict-first (__stcs).
// ---------------------------------------------------------------------------
__global__ void k_norm(const float* __restrict__ x,
                       const float* __restrict__ gamma,
                       const float* __restrict__ beta,
                       float* __restrict__ out) {
    int bc = (NB*NC - 1) - blockIdx.x;   // batch 7 first (L2-hot from chanstat)
    int b = bc >> 8, c = bc & 255;
    const float4* xp = (const float4*)(x + (size_t)bc * HW);
    const float4* sp = (const float4*)(g_s + (size_t)b * HW);
    float4* op = (float4*)(out + (size_t)bc * HW);

    float sum = 0.f, ss = 0.f;
#pragma unroll
    for (int it = 0; it < 8; it++) {
        int i = it*512 + threadIdx.x;
        float4 xv = xp[i], sv = sp[i];
        float vx = xv.x*sv.x, vy = xv.y*sv.y, vz = xv.z*sv.z, vw = xv.w*sv.w;
        sum += (vx + vy) + (vz + vw);
        ss  += vx*vx + vy*vy + vz*vz + vw*vw;
    }
    // block reduction: warp shfl then 16 partials
    for (int o = 16; o > 0; o >>= 1) {
        sum += __shfl_down_sync(0xffffffffu, sum, o);
        ss  += __shfl_down_sync(0xffffffffu, ss,  o);
    }
    __shared__ float rs[16], rq[16];
    __shared__ float s_g, s_b;
    int wid = threadIdx.x >> 5, lid = threadIdx.x & 31;
    if (lid == 0) { rs[wid] = sum; rq[wid] = ss; }
    __syncthreads();
    if (threadIdx.x == 0) {
        float S = 0.f, Q = 0.f;
#pragma unroll
        for (int i = 0; i < 16; i++) { S += rs[i]; Q += rq[i]; }
        float mu  = S * (1.f/HW);
        float var = Q * (1.f/HW) - mu*mu;
        float inv = rsqrtf(var + 1e-5f);
        float gg  = gamma[c] * inv;
        s_g = 5.f * gg;
        s_b = 5.f * (beta[c] - mu * gg);
    }
    __syncthreads();
    float gg = s_g, bb = s_b;
#pragma unroll
    for (int it = 0; it < 8; it++) {
        int i = it*512 + threadIdx.x;
        float4 xv = xp[i], sv = sp[i];   // L1/L2 hit (same 64KB read in phase 1)
        float4 ov = make_float4(fmaxf(0.f, xv.x*sv.x*gg + bb),
                                fmaxf(0.f, xv.y*sv.y*gg + bb),
                                fmaxf(0.f, xv.z*sv.z*gg + bb),
                                fmaxf(0.f, xv.w*sv.w*gg + bb));
        __stcs(op + i, ov);              // evict-first: don't pollute L2
    }
}

extern "C" void kernel_launch(void* const* d_in, const int* in_sizes, int n_in,
                              void* d_out, int out_size) {
    const float* x     = (const float*)d_in[0];
    const float* masks = (const float*)d_in[1];
    const float* cw    = (const float*)d_in[2];
    const float* gamma = (const float*)d_in[3];
    const float* beta  = (const float*)d_in[4];
    float* out = (float*)d_out;

    // maximize L1 for k_norm's phase-2 reuse (smem use is negligible)
    cudaFuncSetAttribute(k_norm, cudaFuncAttributePreferredSharedMemoryCarveout,
                         cudaSharedmemCarveoutMaxL1);

    k_stat_resize<<<RES_BLKS + STAT_BLKS, 256>>>(x, masks);
    k_conv       <<<NB*64, 256>>>(cw);
    k_norm       <<<NB*NC, 512>>>(x, gamma, beta, out);
}

// round 13
// speedup vs baseline: 1.0339x; 1.0339x over previous
#include <cuda_runtime.h>
#include <math.h>

#define NB 8
#define NC 256
#define HD 128
#define HW (HD*HD)
#define HM 512

// scratch (allocation-free rule: __device__ globals)
__device__ __align__(16) float g_m[NB*HW];     // resized mask
__device__ __align__(16) float g_avg[NB*HW];   // RAW mean_c(x)  (premult in conv)
__device__ __align__(16) float g_maxp[NB*HW];  // RAW max_c(x)   (premult in conv)
__device__ __align__(16) float g_s[NB*HW];     // m * sigmoid(conv)

// ---------------------------------------------------------------------------
// Fused Kernel A+B: blocks [0,2048) do channel mean/max (raw, no m);
// blocks [2048,2560) do the antialiased 512->128 mask resize.
// No intra-kernel dependency (premultiply deferred to conv), so resize rides
// free in chanstat's latency shadow. Chanstat: 256 thr = 64 px x 4 ch-groups.
// ---------------------------------------------------------------------------
__global__ void __launch_bounds__(256)
k_stat_resize(const float* __restrict__ x, const float* __restrict__ masks) {
    if (blockIdx.x < NB*HW/64) {
        // ---- chanstat role ----
        __shared__ float s_sum[4][64];
        __shared__ float s_max[4][64];
        int pix = threadIdx.x & 63;
        int cg  = threadIdx.x >> 6;          // 0..3
        int p0  = blockIdx.x * 64;           // never straddles a batch
        int b   = p0 / HW;
        int hw  = p0 - b * HW + pix;

        const float* xp = x + ((size_t)(b*NC + cg*64)) * HW + hw;
        float s = 0.f, mx = -3.4e38f;
#pragma unroll 16
        for (int c = 0; c < 64; c++) {
            float v = __ldg(xp + (size_t)c * HW);
            s += v;
            mx = fmaxf(mx, v);
        }
        s_sum[cg][pix] = s;
        s_max[cg][pix] = mx;
        __syncthreads();
        if (cg == 0) {
            float S  = s_sum[0][pix] + s_sum[1][pix] + s_sum[2][pix] + s_sum[3][pix];
            float M  = fmaxf(fmaxf(s_max[0][pix], s_max[1][pix]),
                             fmaxf(s_max[2][pix], s_max[3][pix]));
            int g = p0 + pix;
            g_avg[g]  = S * (1.f/NC);
            g_maxp[g] = M;
        }
    } else {
        // ---- resize role: antialiased bilinear (triangle, 8 taps/dim) ----
        int idx = (blockIdx.x - NB*HW/64) * 256 + threadIdx.x;
        int b = idx / HW;
        int r = (idx / HD) % HD;
        int q = idx % HD;
        const float raw[8] = {0.125f,0.375f,0.625f,0.875f,0.875f,0.625f,0.375f,0.125f};
        float wr[8], wc[8]; int jr[8], jc[8];
        float tr = 0.f, tc = 0.f;
#pragma unroll
        for (int k = 0; k < 8; k++) {
            int j = 4*r - 2 + k;
            bool ok = (j >= 0) && (j < HM);
            wr[k] = ok ? raw[k] : 0.f;
            jr[k] = ok ? j : 0;
            tr += wr[k];
            j = 4*q - 2 + k;
            ok = (j >= 0) && (j < HM);
            wc[k] = ok ? raw[k] : 0.f;
            jc[k] = ok ? j : 0;
            tc += wc[k];
        }
        const float* mp = masks + (size_t)b * HM * HM;
        float acc = 0.f;
#pragma unroll
        for (int a = 0; a < 8; a++) {
            float rowacc = 0.f;
#pragma unroll
            for (int bb = 0; bb < 8; bb++)
                rowacc += wc[bb] * __ldg(mp + jr[a]*HM + jc[bb]);
            acc += wr[a] * rowacc;
        }
        g_m[idx] = acc / (tr * tc);
    }
}

// ---------------------------------------------------------------------------
// Kernel C: 7x7 conv over [m*avg, m*max, m] (zero pad 3) -> sigmoid ->
// s = m*atten. Premultiply by m happens here while filling smem.
// 16x16 output tile per block, 22x22x3 smem halo tile.
// ---------------------------------------------------------------------------
__global__ void k_conv(const float* __restrict__ cw) {
    __shared__ float sh[3][22][22];
    __shared__ float wsm[3*49];
    int t = threadIdx.x;                 // 256 threads
    int bx = blockIdx.x & 7;
    int by = (blockIdx.x >> 3) & 7;
    int b  = blockIdx.x >> 6;
    int h0 = by*16 - 3, w0 = bx*16 - 3;
    if (t < 147) wsm[t] = cw[t];
    for (int i = t; i < 22*22; i += 256) {
        int ih = i / 22, iw = i % 22;
        int hh = h0 + ih, ww = w0 + iw;
        bool ok = (hh >= 0) && (hh < HD) && (ww >= 0) && (ww < HD);
        if (ok) {
            int g = b*HW + hh*HD + ww;
            float m = g_m[g];
            sh[0][ih][iw] = m * g_avg[g];
            sh[1][ih][iw] = m * g_maxp[g];
            sh[2][ih][iw] = m;
        } else {
            sh[0][ih][iw] = 0.f;
            sh[1][ih][iw] = 0.f;
            sh[2][ih][iw] = 0.f;
        }
    }
    __syncthreads();
    int ty = t >> 4, tx = t & 15;
    float acc = 0.f;
#pragma unroll
    for (int c = 0; c < 3; c++)
#pragma unroll
        for (int kh = 0; kh < 7; kh++)
#pragma unroll
            for (int kw = 0; kw < 7; kw++)
                acc += sh[c][ty+kh][tx+kw] * wsm[c*49 + kh*7 + kw];
    float at = 1.f / (1.f + expf(-acc));
    int h = h0 + 3 + ty, w = w0 + 3 + tx;
    int g = b*HW + h*HD + w;
    g_s[g] = g_m[g] * at;
}

// ---------------------------------------------------------------------------
// Kernel D: per (b,c): out = relu(5 * IN(x*s)). Two-pass with L2 reuse.
// REVERSE batch order: chanstat finishes with tail batches of x hot in L2,
// and norm finishing at batch 0 leaves head batches hot for the NEXT
// iteration's chanstat. Phase 2 re-reads the same 64KB channel (L1/L2-hot).
// out written evict-first (__stcs) to not pollute L2.
// ---------------------------------------------------------------------------
__global__ void k_norm(const float* __restrict__ x,
                       const float* __restrict__ gamma,
                       const float* __restrict__ beta,
                       float* __restrict__ out) {
    int bc = (NB*NC - 1) - blockIdx.x;   // batch 7 first (L2-hot from chanstat)
    int b = bc >> 8, c = bc & 255;
    const float4* xp = (const float4*)(x + (size_t)bc * HW);
    const float4* sp = (const float4*)(g_s + (size_t)b * HW);
    float4* op = (float4*)(out + (size_t)bc * HW);

    float sum = 0.f, ss = 0.f;
#pragma unroll
    for (int it = 0; it < 8; it++) {
        int i = it*512 + threadIdx.x;
        float4 xv = xp[i], sv = sp[i];
        float vx = xv.x*sv.x, vy = xv.y*sv.y, vz = xv.z*sv.z, vw = xv.w*sv.w;
        sum += (vx + vy) + (vz + vw);
        ss  += vx*vx + vy*vy + vz*vz + vw*vw;
    }
    // block reduction: warp shfl then 16 partials
    for (int o = 16; o > 0; o >>= 1) {
        sum += __shfl_down_sync(0xffffffffu, sum, o);
        ss  += __shfl_down_sync(0xffffffffu, ss,  o);
    }
    __shared__ float rs[16], rq[16];
    __shared__ float s_g, s_b;
    int wid = threadIdx.x >> 5, lid = threadIdx.x & 31;
    if (lid == 0) { rs[wid] = sum; rq[wid] = ss; }
    __syncthreads();
    if (threadIdx.x == 0) {
        float S = 0.f, Q = 0.f;
#pragma unroll
        for (int i = 0; i < 16; i++) { S += rs[i]; Q += rq[i]; }
        float mu  = S * (1.f/HW);
        float var = Q * (1.f/HW) - mu*mu;
        float inv = rsqrtf(var + 1e-5f);
        float gg  = gamma[c] * inv;
        s_g = 5.f * gg;
        s_b = 5.f * (beta[c] - mu * gg);
    }
    __syncthreads();
    float gg = s_g, bb = s_b;
#pragma unroll
    for (int it = 0; it < 8; it++) {
        int i = it*512 + threadIdx.x;
        float4 xv = xp[i], sv = sp[i];   // L1/L2 hit (same 64KB read in phase 1)
        float4 ov = make_float4(fmaxf(0.f, xv.x*sv.x*gg + bb),
                                fmaxf(0.f, xv.y*sv.y*gg + bb),
                                fmaxf(0.f, xv.z*sv.z*gg + bb),
                                fmaxf(0.f, xv.w*sv.w*gg + bb));
        __stcs(op + i, ov);              // evict-first: don't pollute L2
    }
}

extern "C" void kernel_launch(void* const* d_in, const int* in_sizes, int n_in,
                              void* d_out, int out_size) {
    const float* x     = (const float*)d_in[0];
    const float* masks = (const float*)d_in[1];
    const float* cw    = (const float*)d_in[2];
    const float* gamma = (const float*)d_in[3];
    const float* beta  = (const float*)d_in[4];
    float* out = (float*)d_out;

    k_stat_resize<<<NB*HW/64 + NB*HW/256, 256>>>(x, masks);
    k_conv       <<<NB*64, 256>>>(cw);
    k_norm       <<<NB*NC, 512>>>(x, gamma, beta, out);
}